// round 5
// baseline (speedup 1.0000x reference)
#include <cuda_runtime.h>

// ---------------------------------------------------------------------------
// FFT long conv. Filter for (b,d) is b*32 + (d>>3); pack adjacent channel
// pairs (d,d+1) as z = u[...,d] + i*u[...,d+1] (contiguous float2 in u).
//   w = IFFT( FFT(z) .* H_phi ),  Re->d, Im->d+1.  row r = b*128+(d>>1), phi=r>>2.
// Radix plan [32, 32, 16]: stage1 radix-32 global->smem (half-zero),
// stage2 radix-32 smem, stage3 radix-16 unit-twiddle fused with ×H and its
// inverse in registers, then inverse radix-32 stages, last writes the window
// [4095, 4095+8192) directly to global. Scalar float2 math.
// ---------------------------------------------------------------------------

#define NFFT 16384
#define LSEQ 8192
#define KLEN 8192
#define DDIM 256
#define BATCH 8
#define CPAIR 128
#define NROWS (BATCH * CPAIR)     // 1024
#define START ((KLEN - 1) / 2)    // 4095
#define NTHREADS 512

#define PHYS(i) ((i) + ((i) >> 4))
#define SMEM_F2 (NFFT + (NFFT >> 4))
#define SMEM_BYTES (SMEM_F2 * (int)sizeof(float2))    // 139264 B

__device__ float2 g_Z[NROWS * LSEQ];   // packed input rows   (64 MB)
__device__ float2 g_W[NROWS * LSEQ];   // packed output rows  (64 MB)
__device__ float2 g_H[DDIM * NFFT];    // filter spectra, plan order, /N  (32 MB)

__device__ __forceinline__ float2 cmulf(float2 a, float2 b) {
    return make_float2(fmaf(a.x, b.x, -a.y * b.y), fmaf(a.x, b.y, a.y * b.x));
}

template<int DIR>
__device__ __forceinline__ void dft4(float2& a, float2& b, float2& c, float2& d) {
    float2 t0 = make_float2(a.x + c.x, a.y + c.y);
    float2 t1 = make_float2(a.x - c.x, a.y - c.y);
    float2 t2 = make_float2(b.x + d.x, b.y + d.y);
    float2 t3 = make_float2(b.x - d.x, b.y - d.y);
    a = make_float2(t0.x + t2.x, t0.y + t2.y);
    c = make_float2(t0.x - t2.x, t0.y - t2.y);
    if (DIR < 0) {
        b = make_float2(t1.x + t3.y, t1.y - t3.x);
        d = make_float2(t1.x - t3.y, t1.y + t3.x);
    } else {
        b = make_float2(t1.x - t3.y, t1.y + t3.x);
        d = make_float2(t1.x + t3.y, t1.y - t3.x);
    }
}

template<int DIR>
__device__ __forceinline__ float2 twc(float2 a, float c, float s) {
    const float si = (DIR < 0) ? -s : s;
    return make_float2(a.x * c - a.y * si, a.x * si + a.y * c);
}

// second layer of DFT16 (twiddles + row dft4s)
template<int DIR>
__device__ __forceinline__ void dft16_layer2(float2 v[16]) {
    const float C1 = 0.9238795325112867f, S1 = 0.3826834323650898f;
    const float R2 = 0.7071067811865476f;
    v[5]  = twc<DIR>(v[5],  C1,  S1);
    v[9]  = twc<DIR>(v[9],  R2,  R2);
    v[13] = twc<DIR>(v[13], S1,  C1);
    v[6]  = twc<DIR>(v[6],  R2,  R2);
    v[10] = (DIR < 0) ? make_float2(v[10].y, -v[10].x)
                      : make_float2(-v[10].y, v[10].x);
    v[14] = twc<DIR>(v[14], -R2,  R2);
    v[7]  = twc<DIR>(v[7],   S1,  C1);
    v[11] = twc<DIR>(v[11], -R2,  R2);
    v[15] = twc<DIR>(v[15], -C1, -S1);
    dft4<DIR>(v[0],  v[1],  v[2],  v[3]);
    dft4<DIR>(v[4],  v[5],  v[6],  v[7]);
    dft4<DIR>(v[8],  v[9],  v[10], v[11]);
    dft4<DIR>(v[12], v[13], v[14], v[15]);
}

// Full DFT16. Output slot s16(r) = 4*(r&3)+(r>>2) holds spectral index r.
template<int DIR>
__device__ __forceinline__ void dft16(float2 v[16]) {
    dft4<DIR>(v[0], v[4], v[8],  v[12]);
    dft4<DIR>(v[1], v[5], v[9],  v[13]);
    dft4<DIR>(v[2], v[6], v[10], v[14]);
    dft4<DIR>(v[3], v[7], v[11], v[15]);
    dft16_layer2<DIR>(v);
}

__device__ __forceinline__ constexpr int slot16(int r) { return ((r & 3) << 2) | (r >> 2); }
// DFT32 slot map: r = 2k+p -> p*16 + slot16(k)
__device__ __forceinline__ constexpr int slot32(int r) { return ((r & 1) << 4) | slot16(r >> 1); }

// W32^n = cospi(n/16) -+ i sinpi(n/16) constant tables
#define C32_1 0.9807852804032304f
#define S32_1 0.1950903220161283f
#define C32_2 0.9238795325112867f
#define S32_2 0.3826834323650898f
#define C32_3 0.8314696123025452f
#define S32_3 0.5555702330196022f
#define R2C   0.7071067811865476f

// DFT32: radix-2 layer + two DFT16s. Output slot32(r) holds spectral index r.
template<int DIR>
__device__ __forceinline__ void dft32(float2 v[32]) {
    const float CW[16] = { 1.f, C32_1, C32_2, C32_3, R2C, S32_3, S32_2, S32_1,
                           0.f, -S32_1, -S32_2, -S32_3, -R2C, -C32_3, -C32_2, -C32_1 };
    const float SW[16] = { 0.f, S32_1, S32_2, S32_3, R2C, C32_3, C32_2, C32_1,
                           1.f, C32_1, C32_2, C32_3, R2C, S32_3, S32_2, S32_1 };
    #pragma unroll
    for (int n = 0; n < 16; n++) {
        float2 e = make_float2(v[n].x + v[n + 16].x, v[n].y + v[n + 16].y);
        float2 o = make_float2(v[n].x - v[n + 16].x, v[n].y - v[n + 16].y);
        v[n] = e;
        if (n == 0)      v[16] = o;
        else if (n == 8) v[24] = (DIR < 0) ? make_float2(o.y, -o.x) : make_float2(-o.y, o.x);
        else             v[n + 16] = twc<DIR>(o, CW[n], SW[n]);
    }
    dft16<DIR>(v);
    dft16<DIR>(v + 16);
}

// Forward DFT32 with v[16..31] == 0 (zero-padded upper half): layer1 degenerates.
__device__ __forceinline__ void dft32_fwd_hz(float2 v[32]) {
    const float CW[16] = { 1.f, C32_1, C32_2, C32_3, R2C, S32_3, S32_2, S32_1,
                           0.f, -S32_1, -S32_2, -S32_3, -R2C, -C32_3, -C32_2, -C32_1 };
    const float SW[16] = { 0.f, S32_1, S32_2, S32_3, R2C, C32_3, C32_2, C32_1,
                           1.f, C32_1, C32_2, C32_3, R2C, S32_3, S32_2, S32_1 };
    #pragma unroll
    for (int n = 0; n < 16; n++) {
        float2 a = v[n];
        if (n == 0)      v[16] = a;
        else if (n == 8) v[24] = make_float2(a.y, -a.x);
        else             v[n + 16] = twc<-1>(a, CW[n], SW[n]);
    }
    dft16<-1>(v);
    dft16<-1>(v + 16);
}

// ---- stages ---------------------------------------------------------------
// Stage 1 fwd (M=16384, Ms=512): one butterfly per thread, loads global.
__device__ __forceinline__ void fwd_stage1_global(const float2* __restrict__ src,
                                                  float2* s, int tid) {
    const int j = tid;
    float2 v[32];
    #pragma unroll
    for (int m = 0; m < 16; m++) v[m] = src[j + m * 512];
    dft32_fwd_hz(v);
    float sv, cv;
    sincospif((float)j * (2.0f / (float)NFFT), &sv, &cv);
    float2 w1 = make_float2(cv, -sv);
    s[PHYS(j)] = v[0];
    float2 wr = w1;
    #pragma unroll
    for (int r = 1; r < 32; r++) {
        s[PHYS(j + r * 512)] = cmulf(v[slot32(r)], wr);
        wr = cmulf(wr, w1);
    }
    __syncthreads();
}

// Same for real input rows (h)
__device__ __forceinline__ void fwd_stage1_global_real(const float* __restrict__ src,
                                                       float2* s, int tid) {
    const int j = tid;
    float2 v[32];
    #pragma unroll
    for (int m = 0; m < 16; m++) v[m] = make_float2(src[j + m * 512], 0.f);
    dft32_fwd_hz(v);
    float sv, cv;
    sincospif((float)j * (2.0f / (float)NFFT), &sv, &cv);
    float2 w1 = make_float2(cv, -sv);
    s[PHYS(j)] = v[0];
    float2 wr = w1;
    #pragma unroll
    for (int r = 1; r < 32; r++) {
        s[PHYS(j + r * 512)] = cmulf(v[slot32(r)], wr);
        wr = cmulf(wr, w1);
    }
    __syncthreads();
}

// Stage 2 (M=512, Ms=16), one butterfly per thread, smem in/out.
template<int DIR>
__device__ __forceinline__ void stage2_r32(float2* s, int tid) {
    const int j = tid & 15;
    const int base = (tid >> 4) * 512 + j;
    float sv, cv;
    sincospif((float)j * (2.0f / 512.0f), &sv, &cv);
    float2 w1 = make_float2(cv, (DIR < 0) ? -sv : sv);
    float2 v[32];
    if (DIR < 0) {
        #pragma unroll
        for (int m = 0; m < 32; m++) v[m] = s[PHYS(base + m * 16)];
        dft32<DIR>(v);
        s[PHYS(base)] = v[0];
        float2 wr = w1;
        #pragma unroll
        for (int r = 1; r < 32; r++) {
            s[PHYS(base + r * 16)] = cmulf(v[slot32(r)], wr);
            wr = cmulf(wr, w1);
        }
    } else {
        v[0] = s[PHYS(base)];
        float2 wr = w1;
        #pragma unroll
        for (int r = 1; r < 32; r++) {
            v[r] = cmulf(s[PHYS(base + r * 16)], wr);
            wr = cmulf(wr, w1);
        }
        dft32<DIR>(v);
        #pragma unroll
        for (int m = 0; m < 32; m++) s[PHYS(base + m * 16)] = v[slot32(m)];
    }
    __syncthreads();
}

// Stage 3 fused (M=16, unit twiddles): fwd DFT16 -> ×H -> inv DFT16, registers.
__device__ __forceinline__ void fused_mul(float2* s, const float2* __restrict__ Hd, int tid) {
    #pragma unroll
    for (int it = 0; it < 2; it++) {
        const int base = (tid + it * NTHREADS) * 16;
        float2 v[16];
        #pragma unroll
        for (int k = 0; k < 16; k++) v[k] = s[PHYS(base + k)];
        dft16<-1>(v);
        float2 u[16];
        #pragma unroll
        for (int r = 0; r < 16; r++)
            u[r] = cmulf(v[slot16(r)], Hd[base + r]);   // H stored at position r
        dft16<1>(u);
        #pragma unroll
        for (int m = 0; m < 16; m++) s[PHYS(base + m)] = u[slot16(m)];
    }
    __syncthreads();
}

// Inverse stage 1 (M=16384): pre-twiddle, inverse DFT32, window -> global.
__device__ __forceinline__ void inv_stage1_global(float2* s, float2* __restrict__ dst,
                                                  int tid) {
    const int j = tid;
    float sv, cv;
    sincospif((float)j * (2.0f / (float)NFFT), &sv, &cv);
    float2 w1 = make_float2(cv, sv);
    float2 v[32];
    v[0] = s[PHYS(j)];
    float2 wr = w1;
    #pragma unroll
    for (int r = 1; r < 32; r++) {
        v[r] = cmulf(s[PHYS(j + r * 512)], wr);
        wr = cmulf(wr, w1);
    }
    dft32<1>(v);
    #pragma unroll
    for (int m = 0; m < 32; m++) {
        int l = j + m * 512 - START;
        if ((unsigned)l < (unsigned)LSEQ) dst[l] = v[slot32(m)];
    }
}

// ---------------------------------------------------------------------------
// Kernel 1: per-batch float2 transpose.  u viewed as (B, L, 128) float2.
// ---------------------------------------------------------------------------
__global__ void __launch_bounds__(256) k_pack(const float* __restrict__ u) {
    __shared__ float2 tile[32][33];
    const int b  = blockIdx.z;
    const int c0 = blockIdx.y * 32;
    const int l0 = blockIdx.x * 32;
    const int tx = threadIdx.x, ty = threadIdx.y;
    const float2* __restrict__ u2 = (const float2*)u;
    #pragma unroll
    for (int i = 0; i < 4; i++) {
        int l = l0 + ty + 8 * i;
        tile[tx][ty + 8 * i] = u2[((size_t)b * LSEQ + l) * CPAIR + (c0 + tx)];
    }
    __syncthreads();
    #pragma unroll
    for (int i = 0; i < 4; i++) {
        int c = c0 + ty + 8 * i;
        int l = l0 + tx;
        g_Z[((size_t)b * CPAIR + c) * LSEQ + l] = tile[ty + 8 * i][tx];
    }
}

// ---------------------------------------------------------------------------
// Kernel 2: filter spectra in plan order, pre-scaled 1/N
// ---------------------------------------------------------------------------
__global__ void __launch_bounds__(NTHREADS, 1) k_hfft(const float* __restrict__ h) {
    extern __shared__ float2 s[];
    const int d = blockIdx.x, tid = threadIdx.x;
    fwd_stage1_global_real(h + (size_t)d * KLEN, s, tid);
    stage2_r32<-1>(s, tid);
    const float inv = 1.0f / (float)NFFT;
    float2* __restrict__ Hd = g_H + (size_t)d * NFFT;
    #pragma unroll
    for (int it = 0; it < 2; it++) {
        const int base = (tid + it * NTHREADS) * 16;
        float2 v[16];
        #pragma unroll
        for (int k = 0; k < 16; k++) v[k] = s[PHYS(base + k)];
        dft16<-1>(v);
        #pragma unroll
        for (int r = 0; r < 16; r++) {
            float2 t = v[slot16(r)];
            Hd[base + r] = make_float2(t.x * inv, t.y * inv);
        }
    }
}

// ---------------------------------------------------------------------------
// Kernel 3: per packed row: FFT -> .*H -> IFFT -> window -> g_W
// ---------------------------------------------------------------------------
__global__ void __launch_bounds__(NTHREADS, 1) k_conv() {
    extern __shared__ float2 s[];
    const int row = blockIdx.x;
    const int phi = row >> 2;
    const int tid = threadIdx.x;
    fwd_stage1_global(g_Z + (size_t)row * LSEQ, s, tid);
    stage2_r32<-1>(s, tid);
    fused_mul(s, g_H + (size_t)phi * NFFT, tid);
    stage2_r32<1>(s, tid);
    inv_stage1_global(s, g_W + (size_t)row * LSEQ, tid);
}

// ---------------------------------------------------------------------------
// Kernel 4: per-batch float2 transpose back.
// ---------------------------------------------------------------------------
__global__ void __launch_bounds__(256) k_unpack(float* __restrict__ y) {
    __shared__ float2 tile[32][33];
    const int b  = blockIdx.z;
    const int c0 = blockIdx.y * 32;
    const int l0 = blockIdx.x * 32;
    const int tx = threadIdx.x, ty = threadIdx.y;
    float2* __restrict__ y2 = (float2*)y;
    #pragma unroll
    for (int i = 0; i < 4; i++) {
        int c = c0 + ty + 8 * i;
        int l = l0 + tx;
        tile[ty + 8 * i][tx] = g_W[((size_t)b * CPAIR + c) * LSEQ + l];
    }
    __syncthreads();
    #pragma unroll
    for (int i = 0; i < 4; i++) {
        int l = l0 + ty + 8 * i;
        y2[((size_t)b * LSEQ + l) * CPAIR + (c0 + tx)] = tile[tx][ty + 8 * i];
    }
}

// ---------------------------------------------------------------------------
extern "C" void kernel_launch(void* const* d_in, const int* in_sizes, int n_in,
                              void* d_out, int out_size) {
    (void)in_sizes; (void)n_in; (void)out_size;
    const float* u = (const float*)d_in[0];
    const float* h = (const float*)d_in[1];
    float* y = (float*)d_out;

    cudaFuncSetAttribute(k_hfft, cudaFuncAttributeMaxDynamicSharedMemorySize, SMEM_BYTES);
    cudaFuncSetAttribute(k_conv, cudaFuncAttributeMaxDynamicSharedMemorySize, SMEM_BYTES);

    dim3 tb(32, 8);
    dim3 tg(LSEQ / 32, CPAIR / 32, BATCH);

    k_pack<<<tg, tb>>>(u);
    k_hfft<<<DDIM, NTHREADS, SMEM_BYTES>>>(h);
    k_conv<<<NROWS, NTHREADS, SMEM_BYTES>>>();
    k_unpack<<<tg, tb>>>(y);
}